// round 4
// baseline (speedup 1.0000x reference)
#include <cuda_runtime.h>

#define NN 512
#define NC 16
#define NK 262144   // 2^18
#define XSTR 575    // per-line FFT-exchange stride (float2), padded layout i+(i>>3)

// Scratch grids. gridA: scatter target / row-FFT input. gridB: row-FFT output.
__device__ __align__(16) float2 g_bufA[NC * NN * NN];
__device__ __align__(16) float2 g_bufB[NC * NN * NN];

// ---------------------------------------------------------------------------
// complex helpers
// ---------------------------------------------------------------------------
__device__ __forceinline__ float2 cmul(float2 a, float2 b) {
    return make_float2(fmaf(a.x, b.x, -a.y * b.y), fmaf(a.x, b.y, a.y * b.x));
}
__device__ __forceinline__ float2 cadd(float2 a, float2 b) { return make_float2(a.x + b.x, a.y + b.y); }
__device__ __forceinline__ float2 csub(float2 a, float2 b) { return make_float2(a.x - b.x, a.y - b.y); }
__device__ __forceinline__ float2 muli(float2 a) { return make_float2(-a.y, a.x); }  // * (+i)

// 8-point unnormalized inverse DFT (sign +i), in place.
__device__ __forceinline__ void dft8(float2* x) {
    const float C = 0.70710678118654752440f;
    float2 u0 = cadd(x[0], x[4]);
    float2 u1 = csub(x[0], x[4]);
    float2 u2 = cadd(x[1], x[5]);
    float2 d1 = csub(x[1], x[5]);
    float2 u3 = make_float2(C * (d1.x - d1.y), C * (d1.x + d1.y));
    float2 u4 = cadd(x[2], x[6]);
    float2 u5 = muli(csub(x[2], x[6]));
    float2 u6 = cadd(x[3], x[7]);
    float2 d3 = csub(x[3], x[7]);
    float2 u7 = make_float2(-C * (d3.x + d3.y), C * (d3.x - d3.y));
    float2 v0 = cadd(u0, u4);
    float2 v2 = csub(u0, u4);
    float2 v1 = cadd(u1, u5);
    float2 v3 = csub(u1, u5);
    float2 v4 = cadd(u2, u6);
    float2 v6 = muli(csub(u2, u6));
    float2 v5 = cadd(u3, u7);
    float2 v7 = muli(csub(u3, u7));
    x[0] = cadd(v0, v4);
    x[4] = csub(v0, v4);
    x[1] = cadd(v1, v5);
    x[5] = csub(v1, v5);
    x[2] = cadd(v2, v6);
    x[6] = csub(v2, v6);
    x[3] = cadd(v3, v7);
    x[7] = csub(v3, v7);
}

__device__ __forceinline__ void twiddle7(float2* x, float ang) {
    float2 w;
    __sincosf(ang, &w.y, &w.x);
    float2 cw = w;
    x[1] = cmul(x[1], cw);
#pragma unroll
    for (int j = 2; j < 8; j++) { cw = cmul(cw, w); x[j] = cmul(x[j], cw); }
}

// 512-point FFT core on one line held in smem `ls` (padded i+(i>>3) layout):
// x[] arrives as natural-order stride-64 input; leaves as natural-order output.
__device__ __forceinline__ void fft512_core(float2* x, float2* ls, int t) {
    dft8(x);
    twiddle7(x, 6.283185307179586f * (float)t * (1.0f / 512.0f));
#pragma unroll
    for (int j = 0; j < 8; j++) { int i = 8 * t + j; ls[i + (i >> 3)] = x[j]; }
    __syncthreads();
    {
        const int q = t & 7, p = t >> 3;
#pragma unroll
        for (int r = 0; r < 8; r++) { int i = q + 8 * p + 64 * r; x[r] = ls[i + (i >> 3)]; }
        __syncthreads();
        dft8(x);
        twiddle7(x, 6.283185307179586f * (float)p * (1.0f / 64.0f));
#pragma unroll
        for (int j = 0; j < 8; j++) { int i = q + 64 * p + 8 * j; ls[i + (i >> 3)] = x[j]; }
    }
    __syncthreads();
#pragma unroll
    for (int r = 0; r < 8; r++) { int i = t + 64 * r; x[r] = ls[i + (i >> 3)]; }
    dft8(x);
}

// ---------------------------------------------------------------------------
// Kernel 1: scatter-add, one thread per sample, 16 coils, float2 vector atomics.
// ifftshift folded in as (-1)^(iy+ix) on the weight.
// ---------------------------------------------------------------------------
__global__ void __launch_bounds__(256) scatter_kernel(
    const float* __restrict__ xr, const float* __restrict__ xi,
    const float2* __restrict__ traj, const float* __restrict__ dcf)
{
    int k = blockIdx.x * blockDim.x + threadIdx.x;
    float2 t = traj[k];
    int iy = __float2int_rn((t.x + 0.5f) * (float)NN) & (NN - 1);
    int ix = __float2int_rn((t.y + 0.5f) * (float)NN) & (NN - 1);
    float w = dcf[k];
    if ((iy + ix) & 1) w = -w;
    int cell = iy * NN + ix;
#pragma unroll
    for (int c = 0; c < NC; c++) {
        float2 v = make_float2(xr[c * NK + k] * w, xi[c * NK + k] * w);
        atomicAdd(&g_bufA[c * NN * NN + cell], v);
    }
}

// ---------------------------------------------------------------------------
// Kernel 2: row FFTs, gridA -> gridB. 4 lines/block, 256 threads.
// ---------------------------------------------------------------------------
__global__ void __launch_bounds__(256) fft_row_kernel() {
    __shared__ float2 sh[4 * XSTR];
    const int tid  = threadIdx.x;
    const int coil = blockIdx.y;
    const int row  = blockIdx.x * 4 + tid / 64;
    const int t    = tid & 63;

    const float2* __restrict__ src = g_bufA + coil * NN * NN + row * NN;
    float2*       __restrict__ dst = g_bufB + coil * NN * NN + row * NN;
    float2* ls = sh + (tid / 64) * XSTR;

    float2 x[8];
#pragma unroll
    for (int r = 0; r < 8; r++) x[r] = src[t + 64 * r];
    fft512_core(x, ls, t);
#pragma unroll
    for (int j = 0; j < 8; j++) dst[t + 64 * j] = x[j];
}

// ---------------------------------------------------------------------------
// Kernel 3: fused column FFTs + coil combine, accumulator in SHARED memory.
// Block = 4 columns x 64 lanes = 256 threads, 4 coils per block.
// grid = (128 col-groups, 4 coil-groups) = 512 blocks; at 4 blocks/SM all
// blocks are resident in a single wave. __launch_bounds__(256,4) caps regs
// at 64 so the RF allows 32 warps/SM.
// Accumulates conj(csm)*img in smem across 4 coils, then atomicAdds the
// signed partial into out. fftshift folded in as (-1)^(ny+nx).
// ---------------------------------------------------------------------------
__global__ void __launch_bounds__(256, 4) fft_col_combine_kernel(
    const float* __restrict__ csr, const float* __restrict__ csi,
    float* __restrict__ out)
{
    __shared__ float2 exch[4 * XSTR];       // 18.4 KB
    __shared__ float2 accs[NN * 5];         // 20.5 KB, index [i*5 + line]

    const int tid  = threadIdx.x;
    const int line = tid & 3;               // column within group (fast -> coalesced)
    const int t    = tid >> 2;              // butterfly lane 0..63
    const int col  = blockIdx.x * 4 + line;
    const int c0   = blockIdx.y * 4;

    float2* ls = exch + line * XSTR;

    // zero my accumulator slots (each (i,line) owned by exactly one thread)
#pragma unroll
    for (int j = 0; j < 8; j++) accs[(t + 64 * j) * 5 + line] = make_float2(0.f, 0.f);

    for (int cc = 0; cc < 4; cc++) {
        const int c = c0 + cc;
        const float2* __restrict__ src = g_bufB + c * NN * NN;
        const float*  __restrict__ cr  = csr + c * NN * NN;
        const float*  __restrict__ ci  = csi + c * NN * NN;

        float2 x[8];
#pragma unroll
        for (int r = 0; r < 8; r++) x[r] = src[(t + 64 * r) * NN + col];

        fft512_core(x, ls, t);

#pragma unroll
        for (int j = 0; j < 8; j++) {
            int i   = t + 64 * j;
            int pix = i * NN + col;
            float a = cr[pix], b = ci[pix];
            float2 A = accs[i * 5 + line];
            // conj(csm) * img
            A.x = fmaf(a, x[j].x, fmaf( b, x[j].y, A.x));
            A.y = fmaf(a, x[j].y, fmaf(-b, x[j].x, A.y));
            accs[i * 5 + line] = A;
        }
        __syncthreads();   // protect exch before next coil's stage-1 store
    }

#pragma unroll
    for (int j = 0; j < 8; j++) {
        int ny  = t + 64 * j;
        int pix = ny * NN + col;
        float2 A = accs[ny * 5 + line];
        float sgn = ((ny + col) & 1) ? -1.f : 1.f;
        atomicAdd(&out[pix],           sgn * A.x);
        atomicAdd(&out[NN * NN + pix], sgn * A.y);
    }
}

// ---------------------------------------------------------------------------
extern "C" void kernel_launch(void* const* d_in, const int* in_sizes, int n_in,
                              void* d_out, int out_size)
{
    const float* xr   = (const float*)d_in[0];
    const float* xi   = (const float*)d_in[1];
    const float* csr  = (const float*)d_in[2];
    const float* csi  = (const float*)d_in[3];
    const float* traj = (const float*)d_in[4];
    const float* dcf  = (const float*)d_in[5];
    float* out = (float*)d_out;

    // zero the atomic-accumulation targets (memset nodes are graph-capturable)
    void* pA = nullptr;
    cudaGetSymbolAddress(&pA, g_bufA);
    cudaMemsetAsync(pA,  0, (size_t)NC * NN * NN * sizeof(float2), 0);
    cudaMemsetAsync(out, 0, (size_t)2 * NN * NN * sizeof(float),   0);

    scatter_kernel<<<NK / 256, 256>>>(xr, xi, (const float2*)traj, dcf);
    fft_row_kernel<<<dim3(NN / 4, NC), 256>>>();
    fft_col_combine_kernel<<<dim3(NN / 4, NC / 4), 256>>>(csr, csi, out);
}

// round 5
// speedup vs baseline: 1.1531x; 1.1531x over previous
#include <cuda_runtime.h>

#define NN 512
#define NC 16
#define NK 262144   // 2^18
#define XSTR 575    // per-line FFT-exchange stride (float2), padded layout i+(i>>3)

// Scratch grids. gridA: scatter target / row-FFT input. gridB: row-FFT output.
__device__ __align__(16) float2 g_bufA[NC * NN * NN];
__device__ __align__(16) float2 g_bufB[NC * NN * NN];

// ---------------------------------------------------------------------------
// complex helpers
// ---------------------------------------------------------------------------
__device__ __forceinline__ float2 cmul(float2 a, float2 b) {
    return make_float2(fmaf(a.x, b.x, -a.y * b.y), fmaf(a.x, b.y, a.y * b.x));
}
__device__ __forceinline__ float2 cadd(float2 a, float2 b) { return make_float2(a.x + b.x, a.y + b.y); }
__device__ __forceinline__ float2 csub(float2 a, float2 b) { return make_float2(a.x - b.x, a.y - b.y); }
__device__ __forceinline__ float2 muli(float2 a) { return make_float2(-a.y, a.x); }  // * (+i)

// 8-point unnormalized inverse DFT (sign +i), in place.
__device__ __forceinline__ void dft8(float2* x) {
    const float C = 0.70710678118654752440f;
    float2 u0 = cadd(x[0], x[4]);
    float2 u1 = csub(x[0], x[4]);
    float2 u2 = cadd(x[1], x[5]);
    float2 d1 = csub(x[1], x[5]);
    float2 u3 = make_float2(C * (d1.x - d1.y), C * (d1.x + d1.y));
    float2 u4 = cadd(x[2], x[6]);
    float2 u5 = muli(csub(x[2], x[6]));
    float2 u6 = cadd(x[3], x[7]);
    float2 d3 = csub(x[3], x[7]);
    float2 u7 = make_float2(-C * (d3.x + d3.y), C * (d3.x - d3.y));
    float2 v0 = cadd(u0, u4);
    float2 v2 = csub(u0, u4);
    float2 v1 = cadd(u1, u5);
    float2 v3 = csub(u1, u5);
    float2 v4 = cadd(u2, u6);
    float2 v6 = muli(csub(u2, u6));
    float2 v5 = cadd(u3, u7);
    float2 v7 = muli(csub(u3, u7));
    x[0] = cadd(v0, v4);
    x[4] = csub(v0, v4);
    x[1] = cadd(v1, v5);
    x[5] = csub(v1, v5);
    x[2] = cadd(v2, v6);
    x[6] = csub(v2, v6);
    x[3] = cadd(v3, v7);
    x[7] = csub(v3, v7);
}

__device__ __forceinline__ void twiddle7(float2* x, float ang) {
    float2 w;
    __sincosf(ang, &w.y, &w.x);
    float2 cw = w;
    x[1] = cmul(x[1], cw);
#pragma unroll
    for (int j = 2; j < 8; j++) { cw = cmul(cw, w); x[j] = cmul(x[j], cw); }
}

// 512-point FFT core on one line held in smem `ls` (padded i+(i>>3) layout):
// x[] arrives as natural-order stride-64 input; leaves as natural-order output.
__device__ __forceinline__ void fft512_core(float2* x, float2* ls, int t) {
    dft8(x);
    twiddle7(x, 6.283185307179586f * (float)t * (1.0f / 512.0f));
#pragma unroll
    for (int j = 0; j < 8; j++) { int i = 8 * t + j; ls[i + (i >> 3)] = x[j]; }
    __syncthreads();
    {
        const int q = t & 7, p = t >> 3;
#pragma unroll
        for (int r = 0; r < 8; r++) { int i = q + 8 * p + 64 * r; x[r] = ls[i + (i >> 3)]; }
        __syncthreads();
        dft8(x);
        twiddle7(x, 6.283185307179586f * (float)p * (1.0f / 64.0f));
#pragma unroll
        for (int j = 0; j < 8; j++) { int i = q + 64 * p + 8 * j; ls[i + (i >> 3)] = x[j]; }
    }
    __syncthreads();
#pragma unroll
    for (int r = 0; r < 8; r++) { int i = t + 64 * r; x[r] = ls[i + (i >> 3)]; }
    dft8(x);
}

// ---------------------------------------------------------------------------
// Kernel 1: scatter-add, ONE THREAD PER (sample, coil) for 16x the memory-
// level parallelism (R4 profile: per-sample loop was issue=3.7%, pure
// latency-bound). traj/dcf re-reads are L2 hits (3 MB working set).
// ifftshift folded in as (-1)^(iy+ix) on the weight.
// ---------------------------------------------------------------------------
__global__ void __launch_bounds__(256) scatter_kernel(
    const float* __restrict__ xr, const float* __restrict__ xi,
    const float2* __restrict__ traj, const float* __restrict__ dcf)
{
    int gid = blockIdx.x * blockDim.x + threadIdx.x;   // 0 .. NK*NC-1
    int k = gid & (NK - 1);
    int c = gid >> 18;

    float2 t = traj[k];
    int iy = __float2int_rn((t.x + 0.5f) * (float)NN) & (NN - 1);
    int ix = __float2int_rn((t.y + 0.5f) * (float)NN) & (NN - 1);
    float w = dcf[k];
    if ((iy + ix) & 1) w = -w;

    float2 v = make_float2(xr[c * NK + k] * w, xi[c * NK + k] * w);
    atomicAdd(&g_bufA[c * NN * NN + iy * NN + ix], v);
}

// ---------------------------------------------------------------------------
// Kernel 2: row FFTs, gridA -> gridB. 4 lines/block, 256 threads.
// ---------------------------------------------------------------------------
__global__ void __launch_bounds__(256) fft_row_kernel() {
    __shared__ float2 sh[4 * XSTR];
    const int tid  = threadIdx.x;
    const int coil = blockIdx.y;
    const int row  = blockIdx.x * 4 + tid / 64;
    const int t    = tid & 63;

    const float2* __restrict__ src = g_bufA + coil * NN * NN + row * NN;
    float2*       __restrict__ dst = g_bufB + coil * NN * NN + row * NN;
    float2* ls = sh + (tid / 64) * XSTR;

    float2 x[8];
#pragma unroll
    for (int r = 0; r < 8; r++) x[r] = src[t + 64 * r];
    fft512_core(x, ls, t);
#pragma unroll
    for (int j = 0; j < 8; j++) dst[t + 64 * j] = x[j];
}

// ---------------------------------------------------------------------------
// Kernel 3: fused column FFTs + coil combine (R3 register-accumulator version).
// Block = 8 columns x 64 lanes = 512 threads, 4 coils per block.
// Accumulates conj(csm)*img in registers across its 4 coils, then atomicAdds
// the signed partial into out. fftshift folded in as (-1)^(ny+nx).
// ---------------------------------------------------------------------------
__global__ void __launch_bounds__(512) fft_col_combine_kernel(
    const float* __restrict__ csr, const float* __restrict__ csi,
    float* __restrict__ out)
{
    __shared__ float2 sh[8 * XSTR];
    const int tid  = threadIdx.x;
    const int l0   = blockIdx.x * 8;
    const int c0   = blockIdx.y * 4;
    const int line = tid & 7;           // column within group (fast -> coalesced)
    const int t    = tid >> 3;          // butterfly lane 0..63
    const int col  = l0 + line;

    float2* ls = sh + line * XSTR;
    float2 acc[8];
#pragma unroll
    for (int j = 0; j < 8; j++) acc[j] = make_float2(0.f, 0.f);

    for (int cc = 0; cc < 4; cc++) {
        const int c = c0 + cc;
        const float2* __restrict__ src = g_bufB + c * NN * NN;
        const float*  __restrict__ cr  = csr + c * NN * NN;
        const float*  __restrict__ ci  = csi + c * NN * NN;

        float2 x[8];
#pragma unroll
        for (int r = 0; r < 8; r++) x[r] = src[(t + 64 * r) * NN + col];

        fft512_core(x, ls, t);

#pragma unroll
        for (int j = 0; j < 8; j++) {
            int pix = (t + 64 * j) * NN + col;
            float a = cr[pix], b = ci[pix];
            // conj(csm) * img
            acc[j].x = fmaf(a, x[j].x, fmaf( b, x[j].y, acc[j].x));
            acc[j].y = fmaf(a, x[j].y, fmaf(-b, x[j].x, acc[j].y));
        }
        __syncthreads();   // protect smem before next coil's stage-1 store
    }

#pragma unroll
    for (int j = 0; j < 8; j++) {
        int ny  = t + 64 * j;
        int pix = ny * NN + col;
        float sgn = ((ny + col) & 1) ? -1.f : 1.f;
        atomicAdd(&out[pix],           sgn * acc[j].x);
        atomicAdd(&out[NN * NN + pix], sgn * acc[j].y);
    }
}

// ---------------------------------------------------------------------------
extern "C" void kernel_launch(void* const* d_in, const int* in_sizes, int n_in,
                              void* d_out, int out_size)
{
    const float* xr   = (const float*)d_in[0];
    const float* xi   = (const float*)d_in[1];
    const float* csr  = (const float*)d_in[2];
    const float* csi  = (const float*)d_in[3];
    const float* traj = (const float*)d_in[4];
    const float* dcf  = (const float*)d_in[5];
    float* out = (float*)d_out;

    // zero the atomic-accumulation targets (memset nodes are graph-capturable)
    void* pA = nullptr;
    cudaGetSymbolAddress(&pA, g_bufA);
    cudaMemsetAsync(pA,  0, (size_t)NC * NN * NN * sizeof(float2), 0);
    cudaMemsetAsync(out, 0, (size_t)2 * NN * NN * sizeof(float),   0);

    scatter_kernel<<<(NK * NC) / 256, 256>>>(xr, xi, (const float2*)traj, dcf);
    fft_row_kernel<<<dim3(NN / 4, NC), 256>>>();
    fft_col_combine_kernel<<<dim3(NN / 8, NC / 4), 512>>>(csr, csi, out);
}

// round 6
// speedup vs baseline: 1.2835x; 1.1131x over previous
#include <cuda_runtime.h>

#define NN 512
#define NC 16
#define NK 262144   // 2^18
#define XSTR 575    // per-line FFT-exchange stride (float2), padded layout i+(i>>3)

// Scratch grids. gridA: scatter target / row-FFT input. gridB: row-FFT output.
__device__ __align__(16) float2 g_bufA[NC * NN * NN];
__device__ __align__(16) float2 g_bufB[NC * NN * NN];

// ---------------------------------------------------------------------------
// complex helpers
// ---------------------------------------------------------------------------
__device__ __forceinline__ float2 cmul(float2 a, float2 b) {
    return make_float2(fmaf(a.x, b.x, -a.y * b.y), fmaf(a.x, b.y, a.y * b.x));
}
__device__ __forceinline__ float2 cadd(float2 a, float2 b) { return make_float2(a.x + b.x, a.y + b.y); }
__device__ __forceinline__ float2 csub(float2 a, float2 b) { return make_float2(a.x - b.x, a.y - b.y); }
__device__ __forceinline__ float2 muli(float2 a) { return make_float2(-a.y, a.x); }  // * (+i)

// 8-point unnormalized inverse DFT (sign +i), in place.
__device__ __forceinline__ void dft8(float2* x) {
    const float C = 0.70710678118654752440f;
    float2 u0 = cadd(x[0], x[4]);
    float2 u1 = csub(x[0], x[4]);
    float2 u2 = cadd(x[1], x[5]);
    float2 d1 = csub(x[1], x[5]);
    float2 u3 = make_float2(C * (d1.x - d1.y), C * (d1.x + d1.y));
    float2 u4 = cadd(x[2], x[6]);
    float2 u5 = muli(csub(x[2], x[6]));
    float2 u6 = cadd(x[3], x[7]);
    float2 d3 = csub(x[3], x[7]);
    float2 u7 = make_float2(-C * (d3.x + d3.y), C * (d3.x - d3.y));
    float2 v0 = cadd(u0, u4);
    float2 v2 = csub(u0, u4);
    float2 v1 = cadd(u1, u5);
    float2 v3 = csub(u1, u5);
    float2 v4 = cadd(u2, u6);
    float2 v6 = muli(csub(u2, u6));
    float2 v5 = cadd(u3, u7);
    float2 v7 = muli(csub(u3, u7));
    x[0] = cadd(v0, v4);
    x[4] = csub(v0, v4);
    x[1] = cadd(v1, v5);
    x[5] = csub(v1, v5);
    x[2] = cadd(v2, v6);
    x[6] = csub(v2, v6);
    x[3] = cadd(v3, v7);
    x[7] = csub(v3, v7);
}

__device__ __forceinline__ void twiddle7(float2* x, float ang) {
    float2 w;
    __sincosf(ang, &w.y, &w.x);
    float2 cw = w;
    x[1] = cmul(x[1], cw);
#pragma unroll
    for (int j = 2; j < 8; j++) { cw = cmul(cw, w); x[j] = cmul(x[j], cw); }
}

// 512-point FFT core on one line held in smem `ls` (padded i+(i>>3) layout):
// x[] arrives as natural-order stride-64 input; leaves as natural-order output.
__device__ __forceinline__ void fft512_core(float2* x, float2* ls, int t) {
    dft8(x);
    twiddle7(x, 6.283185307179586f * (float)t * (1.0f / 512.0f));
#pragma unroll
    for (int j = 0; j < 8; j++) { int i = 8 * t + j; ls[i + (i >> 3)] = x[j]; }
    __syncthreads();
    {
        const int q = t & 7, p = t >> 3;
#pragma unroll
        for (int r = 0; r < 8; r++) { int i = q + 8 * p + 64 * r; x[r] = ls[i + (i >> 3)]; }
        __syncthreads();
        dft8(x);
        twiddle7(x, 6.283185307179586f * (float)p * (1.0f / 64.0f));
#pragma unroll
        for (int j = 0; j < 8; j++) { int i = q + 64 * p + 8 * j; ls[i + (i >> 3)] = x[j]; }
    }
    __syncthreads();
#pragma unroll
    for (int r = 0; r < 8; r++) { int i = t + 64 * r; x[r] = ls[i + (i >> 3)]; }
    dft8(x);
}

// ---------------------------------------------------------------------------
// Kernel 1: scatter-add, one thread per (sample, coil).
// ifftshift folded in as a sign-bit XOR on the weight.
// ---------------------------------------------------------------------------
__global__ void __launch_bounds__(256) scatter_kernel(
    const float* __restrict__ xr, const float* __restrict__ xi,
    const float2* __restrict__ traj, const float* __restrict__ dcf)
{
    int gid = blockIdx.x * blockDim.x + threadIdx.x;   // 0 .. NK*NC-1
    int k = gid & (NK - 1);
    int c = gid >> 18;

    float2 t = traj[k];
    int iy = __float2int_rn((t.x + 0.5f) * (float)NN) & (NN - 1);
    int ix = __float2int_rn((t.y + 0.5f) * (float)NN) & (NN - 1);
    float w = __uint_as_float(__float_as_uint(dcf[k]) ^ (((unsigned)(iy + ix) & 1u) << 31));

    float2 v = make_float2(xr[c * NK + k] * w, xi[c * NK + k] * w);
    atomicAdd(&g_bufA[c * NN * NN + iy * NN + ix], v);
}

// ---------------------------------------------------------------------------
// Kernel 2: row FFTs, gridA -> gridB. 4 lines/block, 256 threads.
// ---------------------------------------------------------------------------
__global__ void __launch_bounds__(256) fft_row_kernel() {
    __shared__ float2 sh[4 * XSTR];
    const int tid  = threadIdx.x;
    const int coil = blockIdx.y;
    const int row  = blockIdx.x * 4 + tid / 64;
    const int t    = tid & 63;

    const float2* __restrict__ src = g_bufA + coil * NN * NN + row * NN;
    float2*       __restrict__ dst = g_bufB + coil * NN * NN + row * NN;
    float2* ls = sh + (tid / 64) * XSTR;

    float2 x[8];
#pragma unroll
    for (int r = 0; r < 8; r++) x[r] = src[t + 64 * r];
    fft512_core(x, ls, t);
#pragma unroll
    for (int j = 0; j < 8; j++) dst[t + 64 * j] = x[j];
}

// ---------------------------------------------------------------------------
// Kernel 3: fused column FFTs + coil combine, register accumulator,
// __launch_bounds__(512, 2) to cap regs at 64 -> 2 blocks/SM, 32 warps/SM
// (R3 version ran at regs=128, 1 block/SM, occ 24%, latency-bound).
// Block = 8 columns x 64 lanes = 512 threads, 4 coils per block.
// fftshift folded in as (-1)^(ny+nx) at the atomic store.
// ---------------------------------------------------------------------------
__global__ void __launch_bounds__(512, 2) fft_col_combine_kernel(
    const float* __restrict__ csr, const float* __restrict__ csi,
    float* __restrict__ out)
{
    __shared__ float2 sh[8 * XSTR];
    const int tid  = threadIdx.x;
    const int l0   = blockIdx.x * 8;
    const int c0   = blockIdx.y * 4;
    const int line = tid & 7;           // column within group (fast -> coalesced)
    const int t    = tid >> 3;          // butterfly lane 0..63
    const int col  = l0 + line;

    float2* ls = sh + line * XSTR;
    float2 acc[8];
#pragma unroll
    for (int j = 0; j < 8; j++) acc[j] = make_float2(0.f, 0.f);

    for (int cc = 0; cc < 4; cc++) {
        const int c = c0 + cc;
        const float2* __restrict__ src = g_bufB + c * NN * NN;
        const float*  __restrict__ cr  = csr + c * NN * NN;
        const float*  __restrict__ ci  = csi + c * NN * NN;

        float2 x[8];
#pragma unroll
        for (int r = 0; r < 8; r++) x[r] = src[(t + 64 * r) * NN + col];

        fft512_core(x, ls, t);

#pragma unroll
        for (int j = 0; j < 8; j++) {
            int pix = (t + 64 * j) * NN + col;
            float a = cr[pix], b = ci[pix];
            // conj(csm) * img
            acc[j].x = fmaf(a, x[j].x, fmaf( b, x[j].y, acc[j].x));
            acc[j].y = fmaf(a, x[j].y, fmaf(-b, x[j].x, acc[j].y));
        }
        __syncthreads();   // protect smem before next coil's stage-1 store
    }

#pragma unroll
    for (int j = 0; j < 8; j++) {
        int ny  = t + 64 * j;
        int pix = ny * NN + col;
        float sgn = ((ny + col) & 1) ? -1.f : 1.f;
        atomicAdd(&out[pix],           sgn * acc[j].x);
        atomicAdd(&out[NN * NN + pix], sgn * acc[j].y);
    }
}

// ---------------------------------------------------------------------------
extern "C" void kernel_launch(void* const* d_in, const int* in_sizes, int n_in,
                              void* d_out, int out_size)
{
    const float* xr   = (const float*)d_in[0];
    const float* xi   = (const float*)d_in[1];
    const float* csr  = (const float*)d_in[2];
    const float* csi  = (const float*)d_in[3];
    const float* traj = (const float*)d_in[4];
    const float* dcf  = (const float*)d_in[5];
    float* out = (float*)d_out;

    // zero the atomic-accumulation targets (memset nodes are graph-capturable)
    void* pA = nullptr;
    cudaGetSymbolAddress(&pA, g_bufA);
    cudaMemsetAsync(pA,  0, (size_t)NC * NN * NN * sizeof(float2), 0);
    cudaMemsetAsync(out, 0, (size_t)2 * NN * NN * sizeof(float),   0);

    scatter_kernel<<<(NK * NC) / 256, 256>>>(xr, xi, (const float2*)traj, dcf);
    fft_row_kernel<<<dim3(NN / 4, NC), 256>>>();
    fft_col_combine_kernel<<<dim3(NN / 8, NC / 4), 512>>>(csr, csi, out);
}